// round 2
// baseline (speedup 1.0000x reference)
#include <cuda_runtime.h>
#include <cuda_bf16.h>

#define BB 128
#define NN 4096
#define SS 8
#define DD 64
#define NTOK (BB*NN)
#define NPART 8
#define TOKPB (NN/NPART)
#define CHUNK 64
#define NCHUNK (TOKPB/CHUNK)
#define NROW (BB*SS)

__device__ float g_x[NTOK*DD];
__device__ float g_prep[NPART*NROW*DD];
__device__ float g_denp[NPART*NROW];
__device__ float g_qk[NROW*DD];
__device__ float g_slots[NROW*DD];
__device__ float g_dent[NROW];

typedef unsigned long long u64;
__device__ __forceinline__ u64 pk2(float x, float y){
    u64 r; asm("mov.b64 %0,{%1,%2};" : "=l"(r) : "f"(x), "f"(y)); return r;
}
__device__ __forceinline__ void up2(u64 v, float &x, float &y){
    asm("mov.b64 {%0,%1},%2;" : "=f"(x), "=f"(y) : "l"(v));
}
__device__ __forceinline__ u64 ffma2(u64 a, u64 b, u64 c){
    u64 d; asm("fma.rn.f32x2 %0,%1,%2,%3;" : "=l"(d) : "l"(a), "l"(b), "l"(c)); return d;
}

// ---------------- x = LayerNorm(inputs) ----------------
__global__ void k_prep(const float* __restrict__ inp,
                       const float* __restrict__ nw,
                       const float* __restrict__ nb){
    int gw = (blockIdx.x*blockDim.x + threadIdx.x) >> 5;
    int lane = threadIdx.x & 31;
    int nwarp = (gridDim.x*blockDim.x) >> 5;
    float2 wv = ((const float2*)nw)[lane];
    float2 bv = ((const float2*)nb)[lane];
    for (int t = gw; t < NTOK; t += nwarp){
        float2 v = ((const float2*)inp)[(size_t)t*32 + lane];
        float s = v.x + v.y, q = v.x*v.x + v.y*v.y;
        #pragma unroll
        for (int o = 16; o; o >>= 1){
            s += __shfl_xor_sync(~0u, s, o);
            q += __shfl_xor_sync(~0u, q, o);
        }
        float m = s*(1.f/64.f);
        float rs = rsqrtf(q*(1.f/64.f) - m*m + 1e-5f);
        float2 o2;
        o2.x = (v.x-m)*rs*wv.x + bv.x;
        o2.y = (v.y-m)*rs*wv.y + bv.y;
        ((float2*)g_x)[(size_t)t*32 + lane] = o2;
    }
}

// ---------------- attention accumulation, grid (8 parts, 128 batch) --------
__global__ void __launch_bounds__(256) k_attn(int fin, float* __restrict__ out_w){
    int p = blockIdx.x, b = blockIdx.y;
    int tid = threadIdx.x, lane = tid & 31, w = tid >> 5;
    __shared__ float xs[CHUNK][68];
    __shared__ float qs[SS][64];
    __shared__ u64 ws2[CHUNK][SS];

    #pragma unroll
    for (int i = tid; i < SS*DD; i += 256) qs[i>>6][i&63] = g_qk[b*SS*DD + i];

    u64 acc[SS]; float dsum[SS];
    #pragma unroll
    for (int s = 0; s < SS; s++){ acc[s] = 0ull; dsum[s] = 0.f; }

    int tok0 = p*TOKPB;
    for (int c = 0; c < NCHUNK; c++){
        const float4* src = (const float4*)(g_x + ((size_t)(b*NN + tok0 + c*CHUNK))*DD);
        #pragma unroll
        for (int k = 0; k < 4; k++){
            int idx = tid + k*256;
            *(float4*)&xs[idx>>4][(idx&15)*4] = src[idx];
        }
        __syncthreads();

        if (tid < CHUNK){
            int t = tid;
            u64 la[SS];
            #pragma unroll
            for (int s = 0; s < SS; s++) la[s] = 0ull;
            #pragma unroll
            for (int i = 0; i < 32; i++){
                u64 xv = *(const u64*)&xs[t][2*i];
                #pragma unroll
                for (int s = 0; s < SS; s++)
                    la[s] = ffma2(xv, *(const u64*)&qs[s][2*i], la[s]);
            }
            float lg[SS]; float mx = -1e30f;
            #pragma unroll
            for (int s = 0; s < SS; s++){
                float a, bq; up2(la[s], a, bq);
                lg[s] = a + bq; mx = fmaxf(mx, lg[s]);
            }
            float sum = 0.f;
            #pragma unroll
            for (int s = 0; s < SS; s++){ lg[s] = __expf(lg[s]-mx); sum += lg[s]; }
            float inv = 1.f/sum;
            #pragma unroll
            for (int s = 0; s < SS; s++){
                lg[s] = lg[s]*inv + 1e-8f;
                dsum[s] += lg[s];
                ws2[t][s] = pk2(lg[s], lg[s]);
            }
            if (fin){
                float4* dst = (float4*)(out_w + ((size_t)(b*NN + tok0 + c*CHUNK + t))*SS);
                dst[0] = make_float4(lg[0], lg[1], lg[2], lg[3]);
                dst[1] = make_float4(lg[4], lg[5], lg[6], lg[7]);
            }
        }
        __syncthreads();

        #pragma unroll
        for (int j = 0; j < 8; j++){
            int n = w*8 + j;
            u64 xv = *(const u64*)&xs[n][2*lane];
            #pragma unroll
            for (int s = 0; s < SS; s++) acc[s] = ffma2(xv, ws2[n][s], acc[s]);
        }
        __syncthreads();
    }

    float* red  = &xs[0][0];          // 4096 of 4352 floats
    float* dred = (float*)&ws2[0][0]; // 512 of 1024 floats
    #pragma unroll
    for (int s = 0; s < SS; s++){
        float a, bq; up2(acc[s], a, bq);
        red[w*512 + s*64 + 2*lane]   = a;
        red[w*512 + s*64 + 2*lane+1] = bq;
    }
    if (tid < 64){
        #pragma unroll
        for (int s = 0; s < SS; s++) dred[s*64 + tid] = dsum[s];
    }
    __syncthreads();
    #pragma unroll
    for (int k = 0; k < 2; k++){
        int o = tid + k*256;
        float sum = 0.f;
        #pragma unroll
        for (int ww = 0; ww < 8; ww++) sum += red[ww*512 + o];
        g_prep[p*NROW*DD + b*512 + o] = sum;
    }
    if (tid < 8){
        float sum = 0.f;
        #pragma unroll
        for (int t2 = 0; t2 < 64; t2++) sum += dred[tid*64 + t2];
        g_denp[p*NROW + b*SS + tid] = sum;
    }
}

// ---------------- per-row slot update + next query, grid 1024 x 64 --------
__global__ void __launch_bounds__(64) k_update(int init, int wout,
    const float* __restrict__ eps, const float* __restrict__ mu,
    const float* __restrict__ lv,  const float* __restrict__ vw,
    const float* __restrict__ wih, const float* __restrict__ whh,
    const float* __restrict__ bih, const float* __restrict__ bhh,
    const float* __restrict__ nrw, const float* __restrict__ nrb,
    const float* __restrict__ w1,  const float* __restrict__ w2,
    const float* __restrict__ b2,  const float* __restrict__ nsw,
    const float* __restrict__ nsb, const float* __restrict__ qw,
    const float* __restrict__ kw,  float* __restrict__ out_slots){
    int r = blockIdx.x, d = threadIdx.x;
    __shared__ float av[64], hp[64], hh[64], tt[64], mm[128];
    float h2;
    if (!init){
        float den = 0.f;
        #pragma unroll
        for (int p = 0; p < 8; p++) den += g_denp[p*NROW + r];
        if (d == 0 && wout) g_dent[r] = den;
        float pre = 0.f;
        #pragma unroll
        for (int p = 0; p < 8; p++) pre += g_prep[p*NROW*DD + r*64 + d];
        av[d] = pre/den;
        hp[d] = g_slots[r*64 + d];
        __syncthreads();
        float at = 0.f;
        #pragma unroll
        for (int e = 0; e < 64; e++) at += av[e]*vw[d*64 + e];
        __syncthreads();
        av[d] = at;
        __syncthreads();
        float gr = bih[d], gz = bih[64+d], gn = bih[128+d];
        float hr = bhh[d], hz = bhh[64+d], hn = bhh[128+d];
        #pragma unroll 8
        for (int e = 0; e < 64; e++){
            float a = av[e], hpe = hp[e];
            gr += a*wih[d*64+e];       gz += a*wih[(64+d)*64+e];
            gn += a*wih[(128+d)*64+e]; hr += hpe*whh[d*64+e];
            hz += hpe*whh[(64+d)*64+e]; hn += hpe*whh[(128+d)*64+e];
        }
        float rg = 1.f/(1.f + __expf(-(gr+hr)));
        float zg = 1.f/(1.f + __expf(-(gz+hz)));
        float ng = tanhf(gn + rg*hn);
        float h = (1.f-zg)*ng + zg*hp[d];
        hh[d] = h;
        __syncthreads();
        float s = 0.f, q = 0.f;
        #pragma unroll 8
        for (int e = 0; e < 64; e++){ float x = hh[e]; s += x; q += x*x; }
        float m = s*(1.f/64.f);
        float rs = rsqrtf(q*(1.f/64.f) - m*m + 1e-5f);
        tt[d] = (h-m)*rs*nrw[d] + nrb[d];
        __syncthreads();
        float m0 = 0.f, m1 = 0.f;
        #pragma unroll 8
        for (int e = 0; e < 64; e++){
            float t = tt[e];
            m0 += t*w1[d*64+e]; m1 += t*w1[(64+d)*64+e];
        }
        mm[d] = fmaxf(m0, 0.f); mm[64+d] = fmaxf(m1, 0.f);
        __syncthreads();
        float o = h + b2[d];
        #pragma unroll 8
        for (int j = 0; j < 128; j++) o += mm[j]*w2[d*128+j];
        h2 = o;
    } else {
        h2 = mu[d] + __expf(0.5f*lv[d])*eps[r*64 + d];
    }
    g_slots[r*64 + d] = h2;
    if (wout) out_slots[r*64 + d] = h2;
    // next qk = (LN(h2,ns)@qw^T)@kw / 8
    __syncthreads();
    hh[d] = h2;
    __syncthreads();
    float s2 = 0.f, q2 = 0.f;
    #pragma unroll 8
    for (int e = 0; e < 64; e++){ float x = hh[e]; s2 += x; q2 += x*x; }
    float m2 = s2*(1.f/64.f);
    float rs2 = rsqrtf(q2*(1.f/64.f) - m2*m2 + 1e-5f);
    tt[d] = (h2-m2)*rs2*nsw[d] + nsb[d];
    __syncthreads();
    float qd = 0.f;
    #pragma unroll 8
    for (int e = 0; e < 64; e++) qd += tt[e]*qw[d*64+e];
    av[d] = qd;
    __syncthreads();
    float qk = 0.f;
    #pragma unroll 8
    for (int e = 0; e < 64; e++) qk += av[e]*kw[e*64+d];
    g_qk[r*64 + d] = 0.125f*qk;
}

// ---------------- w = what / denom ----------------
__global__ void __launch_bounds__(256) k_wnorm(float* __restrict__ out_w){
    __shared__ float invd[8];
    int tok = blockIdx.x*256 + threadIdx.x;
    int b = tok >> 12;
    if (threadIdx.x < 8) invd[threadIdx.x] = 1.f/g_dent[b*SS + threadIdx.x];
    __syncthreads();
    float4* pw = (float4*)(out_w + (size_t)tok*SS);
    float4 a = pw[0], c = pw[1];
    a.x *= invd[0]; a.y *= invd[1]; a.z *= invd[2]; a.w *= invd[3];
    c.x *= invd[4]; c.y *= invd[5]; c.z *= invd[6]; c.w *= invd[7];
    pw[0] = a; pw[1] = c;
}

extern "C" void kernel_launch(void* const* d_in, const int* in_sizes, int n_in,
                              void* d_out, int out_size){
    const float* inp = (const float*)d_in[0];
    const float* eps = (const float*)d_in[1];
    const float* mu  = (const float*)d_in[2];
    const float* lv  = (const float*)d_in[3];
    const float* kw  = (const float*)d_in[4];
    const float* vw  = (const float*)d_in[5];
    const float* qw  = (const float*)d_in[6];
    const float* niw = (const float*)d_in[7];
    const float* nib = (const float*)d_in[8];
    const float* nsw = (const float*)d_in[9];
    const float* nsb = (const float*)d_in[10];
    const float* nrw = (const float*)d_in[11];
    const float* nrb = (const float*)d_in[12];
    const float* wih = (const float*)d_in[13];
    const float* whh = (const float*)d_in[14];
    const float* bih = (const float*)d_in[15];
    const float* bhh = (const float*)d_in[16];
    const float* w1  = (const float*)d_in[17];
    const float* w2  = (const float*)d_in[18];
    const float* b2  = (const float*)d_in[19];
    float* out_slots = (float*)d_out;
    float* out_w     = out_slots + NROW*DD;

    k_prep<<<2048, 256>>>(inp, niw, nib);
    k_update<<<NROW, 64>>>(1, 0, eps, mu, lv, vw, wih, whh, bih, bhh,
                           nrw, nrb, w1, w2, b2, nsw, nsb, qw, kw, out_slots);
    for (int step = 0; step < 4; step++){
        int fin = (step == 3);
        k_attn<<<dim3(NPART, BB), 256>>>(fin, out_w);
        k_update<<<NROW, 64>>>(0, fin, eps, mu, lv, vw, wih, whh, bih, bhh,
                               nrw, nrb, w1, w2, b2, nsw, nsb, qw, kw, out_slots);
    }
    k_wnorm<<<NTOK/256, 256>>>(out_w);
}

// round 4
// speedup vs baseline: 1.8640x; 1.8640x over previous
#include <cuda_runtime.h>
#include <cuda_bf16.h>

#define BB 128
#define NN 4096
#define SS 8
#define DD 64
#define NTOK (BB*NN)
#define NPART 8
#define TOKPB (NN/NPART)
#define CHUNK 64
#define NCHUNK (TOKPB/CHUNK)
#define NROW (BB*SS)

__device__ float g_x[NTOK*DD];
__device__ float g_prep[NPART*NROW*DD];
__device__ float g_denp[NPART*NROW];
__device__ float g_qk[NROW*DD];
__device__ float g_slots[NROW*DD];
__device__ float g_dent[NROW];

// transposed weights (coalesced access in k_update)
__device__ float g_vwT[64*64];     // vwT[e*64+d]  = vw[d*64+e]
__device__ float g_wihT[64*192];   // wihT[e*192+j] = wih[j*64+e]
__device__ float g_whhT[64*192];
__device__ float g_w1T[64*128];    // w1T[e*128+j] = w1[j*64+e]
__device__ float g_w2T[128*64];    // w2T[j*64+d]  = w2[d*128+j]
__device__ float g_qwT[64*64];

typedef unsigned long long u64;
__device__ __forceinline__ u64 pk2(float x, float y){
    u64 r; asm("mov.b64 %0,{%1,%2};" : "=l"(r) : "f"(x), "f"(y)); return r;
}
__device__ __forceinline__ void up2(u64 v, float &x, float &y){
    asm("mov.b64 {%0,%1},%2;" : "=f"(x), "=f"(y) : "l"(v));
}
__device__ __forceinline__ u64 ffma2(u64 a, u64 b, u64 c){
    u64 d; asm("fma.rn.f32x2 %0,%1,%2,%3;" : "=l"(d) : "l"(a), "l"(b), "l"(c)); return d;
}

// ---------------- weight transpose (once per call) ----------------
__global__ void k_tr(const float* __restrict__ vw, const float* __restrict__ wih,
                     const float* __restrict__ whh, const float* __restrict__ w1,
                     const float* __restrict__ w2,  const float* __restrict__ qw){
    int i = blockIdx.x*256 + threadIdx.x;            // 0..49151
    if (i < 4096){
        g_vwT[(i&63)*64 + (i>>6)] = vw[i];
    } else if (i < 16384){
        int j = i - 4096;  g_wihT[(j&63)*192 + (j>>6)] = wih[j];
    } else if (i < 28672){
        int j = i - 16384; g_whhT[(j&63)*192 + (j>>6)] = whh[j];
    } else if (i < 36864){
        int j = i - 28672; g_w1T[(j&63)*128 + (j>>6)] = w1[j];
    } else if (i < 45056){
        int j = i - 36864; g_w2T[(j&127)*64 + (j>>7)] = w2[j];
    } else if (i < 49152){
        int j = i - 45056; g_qwT[(j&63)*64 + (j>>6)] = qw[j];
    }
}

// ---------------- x = LayerNorm(inputs) ----------------
__global__ void k_prep(const float* __restrict__ inp,
                       const float* __restrict__ nw,
                       const float* __restrict__ nb){
    int gw = (blockIdx.x*blockDim.x + threadIdx.x) >> 5;
    int lane = threadIdx.x & 31;
    int nwarp = (gridDim.x*blockDim.x) >> 5;
    float2 wv = ((const float2*)nw)[lane];
    float2 bv = ((const float2*)nb)[lane];
    for (int t = gw; t < NTOK; t += nwarp){
        float2 v = ((const float2*)inp)[(size_t)t*32 + lane];
        float s = v.x + v.y, q = v.x*v.x + v.y*v.y;
        #pragma unroll
        for (int o = 16; o; o >>= 1){
            s += __shfl_xor_sync(~0u, s, o);
            q += __shfl_xor_sync(~0u, q, o);
        }
        float m = s*(1.f/64.f);
        float rs = rsqrtf(q*(1.f/64.f) - m*m + 1e-5f);
        float2 o2;
        o2.x = (v.x-m)*rs*wv.x + bv.x;
        o2.y = (v.y-m)*rs*wv.y + bv.y;
        ((float2*)g_x)[(size_t)t*32 + lane] = o2;
    }
}

// ---------------- attention accumulation, grid (8 parts, 128 batch) --------
__global__ void __launch_bounds__(256) k_attn(int fin, float* __restrict__ out_w){
    int p = blockIdx.x, b = blockIdx.y;
    int tid = threadIdx.x, lane = tid & 31, w = tid >> 5;
    __shared__ float xs[CHUNK][68];
    __shared__ float qs[SS][64];
    __shared__ u64 ws2[CHUNK][SS];

    #pragma unroll
    for (int i = tid; i < SS*DD; i += 256) qs[i>>6][i&63] = g_qk[b*SS*DD + i];

    u64 acc[SS]; float dsum[SS];
    #pragma unroll
    for (int s = 0; s < SS; s++){ acc[s] = 0ull; dsum[s] = 0.f; }

    int tok0 = p*TOKPB;
    for (int c = 0; c < NCHUNK; c++){
        const float4* src = (const float4*)(g_x + ((size_t)(b*NN + tok0 + c*CHUNK))*DD);
        #pragma unroll
        for (int k = 0; k < 4; k++){
            int idx = tid + k*256;
            *(float4*)&xs[idx>>4][(idx&15)*4] = src[idx];
        }
        __syncthreads();

        if (tid < CHUNK){
            int t = tid;
            u64 la[SS];
            #pragma unroll
            for (int s = 0; s < SS; s++) la[s] = 0ull;
            #pragma unroll
            for (int i = 0; i < 32; i++){
                u64 xv = *(const u64*)&xs[t][2*i];
                #pragma unroll
                for (int s = 0; s < SS; s++)
                    la[s] = ffma2(xv, *(const u64*)&qs[s][2*i], la[s]);
            }
            float lg[SS]; float mx = -1e30f;
            #pragma unroll
            for (int s = 0; s < SS; s++){
                float a, bq; up2(la[s], a, bq);
                lg[s] = a + bq; mx = fmaxf(mx, lg[s]);
            }
            float sum = 0.f;
            #pragma unroll
            for (int s = 0; s < SS; s++){ lg[s] = __expf(lg[s]-mx); sum += lg[s]; }
            float inv = 1.f/sum;
            #pragma unroll
            for (int s = 0; s < SS; s++){
                lg[s] = lg[s]*inv + 1e-8f;
                dsum[s] += lg[s];
                ws2[t][s] = pk2(lg[s], lg[s]);
            }
            if (fin){
                float4* dst = (float4*)(out_w + ((size_t)(b*NN + tok0 + c*CHUNK + t))*SS);
                dst[0] = make_float4(lg[0], lg[1], lg[2], lg[3]);
                dst[1] = make_float4(lg[4], lg[5], lg[6], lg[7]);
            }
        }
        __syncthreads();

        #pragma unroll
        for (int j = 0; j < 8; j++){
            int n = w*8 + j;
            u64 xv = *(const u64*)&xs[n][2*lane];
            #pragma unroll
            for (int s = 0; s < SS; s++) acc[s] = ffma2(xv, ws2[n][s], acc[s]);
        }
        __syncthreads();
    }

    float* red  = &xs[0][0];
    float* dred = (float*)&ws2[0][0];
    #pragma unroll
    for (int s = 0; s < SS; s++){
        float a, bq; up2(acc[s], a, bq);
        red[w*512 + s*64 + 2*lane]   = a;
        red[w*512 + s*64 + 2*lane+1] = bq;
    }
    if (tid < 64){
        #pragma unroll
        for (int s = 0; s < SS; s++) dred[s*64 + tid] = dsum[s];
    }
    __syncthreads();
    #pragma unroll
    for (int k = 0; k < 2; k++){
        int o = tid + k*256;
        float sum = 0.f;
        #pragma unroll
        for (int ww = 0; ww < 8; ww++) sum += red[ww*512 + o];
        g_prep[p*NROW*DD + b*512 + o] = sum;
    }
    if (tid < 8){
        float sum = 0.f;
        #pragma unroll
        for (int t2 = 0; t2 < 64; t2++) sum += dred[tid*64 + t2];
        g_denp[p*NROW + b*SS + tid] = sum;
    }
}

// ---------------- per-row slot update + next query, grid 1024 x 64 --------
__global__ void __launch_bounds__(64) k_update(int init, int wout,
    const float* __restrict__ eps, const float* __restrict__ mu,
    const float* __restrict__ lv,
    const float* __restrict__ bih, const float* __restrict__ bhh,
    const float* __restrict__ nrw, const float* __restrict__ nrb,
    const float* __restrict__ b2,  const float* __restrict__ nsw,
    const float* __restrict__ nsb, const float* __restrict__ kw,
    float* __restrict__ out_slots){
    int r = blockIdx.x, d = threadIdx.x;
    __shared__ float av[64], hp[64], hh[64], tt[64], mm[128];
    float h2;
    if (!init){
        float den = 0.f;
        #pragma unroll
        for (int p = 0; p < 8; p++) den += g_denp[p*NROW + r];
        if (d == 0 && wout) g_dent[r] = den;
        float pre = 0.f;
        #pragma unroll
        for (int p = 0; p < 8; p++) pre += g_prep[p*NROW*DD + r*64 + d];
        av[d] = pre/den;
        hp[d] = g_slots[r*64 + d];
        __syncthreads();
        float at = 0.f;
        #pragma unroll 8
        for (int e = 0; e < 64; e++) at += av[e]*g_vwT[e*64 + d];
        __syncthreads();
        av[d] = at;
        __syncthreads();
        float gr = bih[d], gz = bih[64+d], gn = bih[128+d];
        float hr = bhh[d], hz = bhh[64+d], hn = bhh[128+d];
        #pragma unroll 8
        for (int e = 0; e < 64; e++){
            float a = av[e], hpe = hp[e];
            const float* wi = &g_wihT[e*192];
            const float* wh = &g_whhT[e*192];
            gr += a*wi[d];      gz += a*wi[64+d];
            gn += a*wi[128+d];  hr += hpe*wh[d];
            hz += hpe*wh[64+d]; hn += hpe*wh[128+d];
        }
        float rg = 1.f/(1.f + __expf(-(gr+hr)));
        float zg = 1.f/(1.f + __expf(-(gz+hz)));
        float ng = tanhf(gn + rg*hn);
        float h = (1.f-zg)*ng + zg*hp[d];
        hh[d] = h;
        __syncthreads();
        float s = 0.f, q = 0.f;
        #pragma unroll 8
        for (int e = 0; e < 64; e++){ float x = hh[e]; s += x; q += x*x; }
        float m = s*(1.f/64.f);
        float rs = rsqrtf(q*(1.f/64.f) - m*m + 1e-5f);
        tt[d] = (h-m)*rs*nrw[d] + nrb[d];
        __syncthreads();
        float m0 = 0.f, m1 = 0.f;
        #pragma unroll 8
        for (int e = 0; e < 64; e++){
            float t = tt[e];
            m0 += t*g_w1T[e*128 + d]; m1 += t*g_w1T[e*128 + 64 + d];
        }
        mm[d] = fmaxf(m0, 0.f); mm[64+d] = fmaxf(m1, 0.f);
        __syncthreads();
        float o = h + b2[d];
        #pragma unroll 8
        for (int j = 0; j < 128; j++) o += mm[j]*g_w2T[j*64 + d];
        h2 = o;
    } else {
        h2 = mu[d] + __expf(0.5f*lv[d])*eps[r*64 + d];
    }
    g_slots[r*64 + d] = h2;
    if (wout) out_slots[r*64 + d] = h2;
    // next qk = (LN(h2,ns)@qw^T)@kw / 8
    __syncthreads();
    hh[d] = h2;
    __syncthreads();
    float s2 = 0.f, q2 = 0.f;
    #pragma unroll 8
    for (int e = 0; e < 64; e++){ float x = hh[e]; s2 += x; q2 += x*x; }
    float m2 = s2*(1.f/64.f);
    float rs2 = rsqrtf(q2*(1.f/64.f) - m2*m2 + 1e-5f);
    tt[d] = (h2-m2)*rs2*nsw[d] + nsb[d];
    __syncthreads();
    float qd = 0.f;
    #pragma unroll 8
    for (int e = 0; e < 64; e++) qd += tt[e]*g_qwT[e*64 + d];
    av[d] = qd;
    __syncthreads();
    float qk = 0.f;
    #pragma unroll 8
    for (int e = 0; e < 64; e++) qk += av[e]*kw[e*64+d];
    g_qk[r*64 + d] = 0.125f*qk;
}

// ---------------- w = what / denom ----------------
__global__ void __launch_bounds__(256) k_wnorm(float* __restrict__ out_w){
    __shared__ float invd[8];
    int tok = blockIdx.x*256 + threadIdx.x;
    int b = tok >> 12;
    if (threadIdx.x < 8) invd[threadIdx.x] = 1.f/g_dent[b*SS + threadIdx.x];
    __syncthreads();
    float4* pw = (float4*)(out_w + (size_t)tok*SS);
    float4 a = pw[0], c = pw[1];
    a.x *= invd[0]; a.y *= invd[1]; a.z *= invd[2]; a.w *= invd[3];
    c.x *= invd[4]; c.y *= invd[5]; c.z *= invd[6]; c.w *= invd[7];
    pw[0] = a; pw[1] = c;
}

extern "C" void kernel_launch(void* const* d_in, const int* in_sizes, int n_in,
                              void* d_out, int out_size){
    const float* inp = (const float*)d_in[0];
    const float* eps = (const float*)d_in[1];
    const float* mu  = (const float*)d_in[2];
    const float* lv  = (const float*)d_in[3];
    const float* kw  = (const float*)d_in[4];
    const float* vw  = (const float*)d_in[5];
    const float* qw  = (const float*)d_in[6];
    const float* niw = (const float*)d_in[7];
    const float* nib = (const float*)d_in[8];
    const float* nsw = (const float*)d_in[9];
    const float* nsb = (const float*)d_in[10];
    const float* nrw = (const float*)d_in[11];
    const float* nrb = (const float*)d_in[12];
    const float* wih = (const float*)d_in[13];
    const float* whh = (const float*)d_in[14];
    const float* bih = (const float*)d_in[15];
    const float* bhh = (const float*)d_in[16];
    const float* w1  = (const float*)d_in[17];
    const float* w2  = (const float*)d_in[18];
    const float* b2  = (const float*)d_in[19];
    float* out_slots = (float*)d_out;
    float* out_w     = out_slots + NROW*DD;

    k_tr<<<192, 256>>>(vw, wih, whh, w1, w2, qw);
    k_prep<<<2048, 256>>>(inp, niw, nib);
    k_update<<<NROW, 64>>>(1, 0, eps, mu, lv, bih, bhh,
                           nrw, nrb, b2, nsw, nsb, kw, out_slots);
    for (int step = 0; step < 4; step++){
        int fin = (step == 3);
        k_attn<<<dim3(NPART, BB), 256>>>(fin, out_w);
        k_update<<<NROW, 64>>>(0, fin, eps, mu, lv, bih, bhh,
                               nrw, nrb, b2, nsw, nsb, kw, out_slots);
    }
    k_wnorm<<<NTOK/256, 256>>>(out_w);
}